// round 17
// baseline (speedup 1.0000x reference)
#include <cuda_runtime.h>
#include <cuda_bf16.h>
#include <cstdint>

// Problem constants
constexpr int B_  = 32;
constexpr int T_  = 1024;
constexpr int F_  = 512;
constexpr int H_  = 512;
constexpr int G4H = 2048;   // 4*H

// Recurrence: 4 independent batch groups x 32 blocks.
#define NB 128
#define NT 256
#define NG 4     // groups
#define BG 8     // batch per group
#define HC 16    // h-cols per block

// ---------------- device scratch ----------------
__device__ float g_z0t[(size_t)T_ * B_ * G4H];     // [t][b][gatecol]
__device__ float g_gh[NG][2][H_ * BG];             // per-group h ping-pong [k][b]
__device__ __align__(128) unsigned g_slots[NG][32];
// bf16 split operands (uint4 arrays for 16B alignment; viewed as bf16)
__device__ uint4 g_xh4[(size_t)32768 * 512 / 8];   // xh[row][512]
__device__ uint4 g_xl4[(size_t)32768 * 512 / 8];   // xl[row][512]
__device__ uint4 g_wh4[(size_t)2048 * 512 / 8];    // wih_t[n][512] (transposed)
__device__ uint4 g_wl4[(size_t)2048 * 512 / 8];    // wil_t[n][512]

// ---------------- helpers ----------------
__device__ __forceinline__ unsigned long long pack2(float x, float y) {
    unsigned long long r;
    asm("mov.b64 %0, {%1, %2};" : "=l"(r) : "f"(x), "f"(y));
    return r;
}
__device__ __forceinline__ unsigned long long fma2(unsigned long long a,
                                                   unsigned long long b,
                                                   unsigned long long c) {
    unsigned long long d;
    asm("fma.rn.f32x2 %0, %1, %2, %3;" : "=l"(d) : "l"(a), "l"(b), "l"(c));
    return d;
}
__device__ __forceinline__ unsigned long long add2(unsigned long long a,
                                                   unsigned long long b) {
    unsigned long long d;
    asm("add.rn.f32x2 %0, %1, %2;" : "=l"(d) : "l"(a), "l"(b));
    return d;
}
__device__ __forceinline__ float2 unpack2(unsigned long long v) {
    float2 f;
    asm("mov.b64 {%0, %1}, %2;" : "=f"(f.x), "=f"(f.y) : "l"(v));
    return f;
}
__device__ __forceinline__ unsigned ld_acq(const unsigned* p) {
    unsigned v;
    asm volatile("ld.acquire.gpu.global.u32 %0, [%1];"
                 : "=r"(v) : "l"(p) : "memory");
    return v;
}
__device__ __forceinline__ void st_rel(unsigned* p, unsigned v) {
    asm volatile("st.release.gpu.global.u32 [%0], %1;"
                 :: "l"(p), "r"(v) : "memory");
}
__device__ __forceinline__ float sigf(float x) {
    return 1.f / (1.f + __expf(-x));
}
__device__ __forceinline__ float tanh_fast(float x) {
    return 2.f / (1.f + __expf(-2.f * x)) - 1.f;
}
__device__ __forceinline__ void mma_bf16(float* c, const unsigned* a,
                                         const unsigned* b) {
    asm volatile(
        "mma.sync.aligned.m16n8k16.row.col.f32.bf16.bf16.f32 "
        "{%0,%1,%2,%3}, {%4,%5,%6,%7}, {%8,%9}, {%0,%1,%2,%3};"
        : "+f"(c[0]), "+f"(c[1]), "+f"(c[2]), "+f"(c[3])
        : "r"(a[0]), "r"(a[1]), "r"(a[2]), "r"(a[3]), "r"(b[0]), "r"(b[1]));
}
__device__ __forceinline__ unsigned bfpack(float a, float b) {
    unsigned short lo = __bfloat16_as_ushort(__float2bfloat16_rn(a));
    unsigned short hi = __bfloat16_as_ushort(__float2bfloat16_rn(b));
    return (unsigned)lo | ((unsigned)hi << 16);
}

// ---------------- prep: bf16 split conversion + state init ----------------
// units: 4,194,304 x-float4 then 262,144 Wi-float4 (transposed on store).
__global__ void __launch_bounds__(256) prep(const float* __restrict__ x,
                                            const float* __restrict__ Wi,
                                            const float* __restrict__ h0) {
    const int tid = threadIdx.x;
    if (blockIdx.x == 0) {
        for (int i = tid; i < NG * H_ * BG; i += 256) {
            int g   = i >> 12;
            int rem = i & 4095;
            int k   = rem >> 3;
            int b   = rem & 7;
            g_gh[g][0][rem] = h0[(size_t)(g * BG + b) * H_ + k];
        }
        if (tid < NG * 32) g_slots[tid >> 5][tid & 31] = 0;
    }

    const size_t NX = (size_t)32768 * 512 / 4;   // x float4 count
    const size_t NW = (size_t)512 * 2048 / 4;    // Wi float4 count
    uint2* xh2 = (uint2*)g_xh4;
    uint2* xl2 = (uint2*)g_xl4;
    __nv_bfloat16* wht = (__nv_bfloat16*)g_wh4;
    __nv_bfloat16* wlt = (__nv_bfloat16*)g_wl4;

    for (size_t i = (size_t)blockIdx.x * 256 + tid; i < NX + NW;
         i += (size_t)gridDim.x * 256) {
        if (i < NX) {
            float4 v = ((const float4*)x)[i];
            float hx = __bfloat162float(__float2bfloat16_rn(v.x));
            float hy = __bfloat162float(__float2bfloat16_rn(v.y));
            float hz = __bfloat162float(__float2bfloat16_rn(v.z));
            float hw = __bfloat162float(__float2bfloat16_rn(v.w));
            uint2 ph, pl;
            ph.x = bfpack(v.x, v.y);
            ph.y = bfpack(v.z, v.w);
            pl.x = bfpack(v.x - hx, v.y - hy);
            pl.y = bfpack(v.z - hz, v.w - hw);
            xh2[i] = ph;
            xl2[i] = pl;
        } else {
            size_t j = i - NX;
            float4 v = ((const float4*)Wi)[j];
            size_t e = j * 4;
            int k = (int)(e >> 11);          // row of Wi
            int n = (int)(e & 2047);         // col of Wi
            float vv[4] = {v.x, v.y, v.z, v.w};
#pragma unroll
            for (int q = 0; q < 4; q++) {
                __nv_bfloat16 hb = __float2bfloat16_rn(vv[q]);
                float hf = __bfloat162float(hb);
                wht[(size_t)(n + q) * 512 + k] = hb;
                wlt[(size_t)(n + q) * 512 + k] = __float2bfloat16_rn(vv[q] - hf);
            }
        }
    }
}

// ---------------- GEMM: bf16 3-way split tensor-core ----------------
// z = xh@wh + xh@wl + xl@wh (+bias), fp32 accum. Block tile 128x64, 8 warps
// (4m x 2n), warp tile 32x32, K chunks of 32. Smem rows padded to 80B
// (frag loads bank-conflict-free: bank = 20g + tig mod 32, all distinct).
__global__ void __launch_bounds__(256, 2) gemm_xwi(const float* __restrict__ bias) {
    __shared__ unsigned short Ah[128][40];
    __shared__ unsigned short Al[128][40];
    __shared__ unsigned short Bh[64][40];
    __shared__ unsigned short Bl[64][40];

    const int tid  = threadIdx.x;
    const int warp = tid >> 5;
    const int lane = tid & 31;
    const int g    = lane >> 2;
    const int tig  = lane & 3;
    const int m0   = (warp >> 1) * 32;
    const int n0   = (warp & 1) * 32;
    const int row0 = blockIdx.y * 128;
    const int col0 = blockIdx.x * 64;

    const __nv_bfloat16* xh = (const __nv_bfloat16*)g_xh4;
    const __nv_bfloat16* xl = (const __nv_bfloat16*)g_xl4;
    const __nv_bfloat16* wh = (const __nv_bfloat16*)g_wh4;
    const __nv_bfloat16* wl = (const __nv_bfloat16*)g_wl4;

    float acc[2][4][4] = {};

    // staging coords: x: thread covers rows sr, sr+64, k-quad skq (8 bf16)
    const int sr  = tid >> 2;
    const int skq = (tid & 3) * 8;
    // Wi: thread covers smem row wn_, k-quad wkq
    const int wn_ = tid >> 2;
    const int wkq = (tid & 3) * 8;

    for (int kb = 0; kb < 16; kb++) {
        __syncthreads();
        {
            size_t e0 = (size_t)(row0 + sr) * 512 + kb * 32 + skq;
            size_t e1 = (size_t)(row0 + sr + 64) * 512 + kb * 32 + skq;
            uint4 h0v = *(const uint4*)(xh + e0);
            uint4 h1v = *(const uint4*)(xh + e1);
            uint4 l0v = *(const uint4*)(xl + e0);
            uint4 l1v = *(const uint4*)(xl + e1);
            *(uint4*)&Ah[sr][skq]      = h0v;
            *(uint4*)&Ah[sr + 64][skq] = h1v;
            *(uint4*)&Al[sr][skq]      = l0v;
            *(uint4*)&Al[sr + 64][skq] = l1v;
            size_t ew = (size_t)(col0 + wn_) * 512 + kb * 32 + wkq;
            uint4 bhv = *(const uint4*)(wh + ew);
            uint4 blv = *(const uint4*)(wl + ew);
            *(uint4*)&Bh[wn_][wkq] = bhv;
            *(uint4*)&Bl[wn_][wkq] = blv;
        }
        __syncthreads();

#pragma unroll
        for (int kc = 0; kc < 2; kc++) {
            const int cb = kc * 16 + tig * 2;
            unsigned ah[2][4], al[2][4], bh[4][2], bl[4][2];
#pragma unroll
            for (int mt = 0; mt < 2; mt++) {
                int rA = m0 + mt * 16 + g;
                ah[mt][0] = *(const unsigned*)&Ah[rA][cb];
                ah[mt][1] = *(const unsigned*)&Ah[rA + 8][cb];
                ah[mt][2] = *(const unsigned*)&Ah[rA][cb + 8];
                ah[mt][3] = *(const unsigned*)&Ah[rA + 8][cb + 8];
                al[mt][0] = *(const unsigned*)&Al[rA][cb];
                al[mt][1] = *(const unsigned*)&Al[rA + 8][cb];
                al[mt][2] = *(const unsigned*)&Al[rA][cb + 8];
                al[mt][3] = *(const unsigned*)&Al[rA + 8][cb + 8];
            }
#pragma unroll
            for (int nt = 0; nt < 4; nt++) {
                int rB = n0 + nt * 8 + g;
                bh[nt][0] = *(const unsigned*)&Bh[rB][cb];
                bh[nt][1] = *(const unsigned*)&Bh[rB][cb + 8];
                bl[nt][0] = *(const unsigned*)&Bl[rB][cb];
                bl[nt][1] = *(const unsigned*)&Bl[rB][cb + 8];
            }
#pragma unroll
            for (int mt = 0; mt < 2; mt++)
#pragma unroll
                for (int nt = 0; nt < 4; nt++) {
                    mma_bf16(acc[mt][nt], ah[mt], bh[nt]);
                    mma_bf16(acc[mt][nt], ah[mt], bl[nt]);
                    mma_bf16(acc[mt][nt], al[mt], bh[nt]);
                }
        }
    }

    // epilogue: c0,c1 -> (row g, cols tig*2..+1); c2,c3 -> row g+8.
#pragma unroll
    for (int mt = 0; mt < 2; mt++) {
#pragma unroll
        for (int nt = 0; nt < 4; nt++) {
            int cc = col0 + n0 + nt * 8 + tig * 2;
            float bx = bias[cc], by = bias[cc + 1];
            int r0 = row0 + m0 + mt * 16 + g;
            int t0 = r0 & (T_ - 1), b0 = r0 >> 10;
            float2 o0;
            o0.x = acc[mt][nt][0] + bx;
            o0.y = acc[mt][nt][1] + by;
            *(float2*)&g_z0t[((size_t)t0 * B_ + b0) * G4H + cc] = o0;
            int r1 = r0 + 8;
            int t1 = r1 & (T_ - 1), b1 = r1 >> 10;
            float2 o1;
            o1.x = acc[mt][nt][2] + bx;
            o1.y = acc[mt][nt][3] + by;
            *(float2*)&g_z0t[((size_t)t1 * B_ + b1) * G4H + cc] = o1;
        }
    }
}

// ---------------- recurrence: EXACT R15 (best validated, 6372us) ----------------
__global__ void __launch_bounds__(NT, 1) lstm_rec(const float* __restrict__ c0,
                                                  const float* __restrict__ Wh,
                                                  float* __restrict__ out) {
    extern __shared__ unsigned char dsm[];
    unsigned long long* Wsu  = (unsigned long long*)dsm;           // [k*32+hc*2+pr]
    unsigned long long* hdup = Wsu + 512 * 32;                     // [k*8+b] (h,h)
    unsigned long long* red  = hdup + 512 * 8;                     // [ks*256+b*32+lane]
    float* hout = (float*)(red + 8 * 256);                         // [b*16+hc]

    const int tid  = threadIdx.x;
    const int ks   = tid >> 5;                 // warp = k-split
    const int lane = tid & 31;
    const int g    = blockIdx.x & 3;           // group
    const int j    = blockIdx.x >> 2;          // block within group (0..31)

    for (int idx = tid; idx < 512 * HC; idx += NT) {
        int k  = idx >> 4;
        int hc = idx & 15;
        int cb = j * HC + hc;
        const float* wr = &Wh[(size_t)k * G4H + cb];
        Wsu[k * 32 + hc * 2 + 0] = pack2(wr[0 * H_], wr[1 * H_]);
        Wsu[k * 32 + hc * 2 + 1] = pack2(wr[2 * H_], wr[3 * H_]);
    }

    const int eb = tid >> 4;
    const int ec = tid & 15;
    const int hg = j * HC + ec;                // global h column
    const int bg = g * BG + eb;                // global batch index
    float c = (tid < 128) ? c0[(size_t)bg * H_ + hg] : 0.f;

    float* c_fin = out;
    float* h_fin = out + B_ * H_;
    float* hist  = out + 2 * B_ * H_;          // [b][t][h]

    unsigned* slots = g_slots[g];

    __syncthreads();

    float z0 = 0.f, z1 = 0.f, z2 = 0.f, z3 = 0.f;
    if (tid < 128) {
        size_t zb = ((size_t)0 * B_ + bg) * G4H + hg;
        z0 = __ldcs(&g_z0t[zb + 0 * H_]);
        z1 = __ldcs(&g_z0t[zb + 1 * H_]);
        z2 = __ldcs(&g_z0t[zb + 2 * H_]);
        z3 = __ldcs(&g_z0t[zb + 3 * H_]);
    }

    for (int t = 0; t < T_; t++) {
        const float4* __restrict__ src4 = (const float4*)g_gh[g][t & 1];
        float* hdst = g_gh[g][(t + 1) & 1];

        if (t > 0) {
            if (tid < 32) {
                const unsigned target = (unsigned)t;
                bool ready;
                do {
                    unsigned v = ld_acq(&slots[tid]);
                    ready = __all_sync(0xffffffffu, v >= target);
                } while (!ready);
            }
            __syncthreads();
        }

#pragma unroll
        for (int q = 0; q < 4; q++) {
            int i = 128 * ks + lane + 32 * q;
            float4 v = __ldcg(&src4[i]);
            ulonglong2* d = (ulonglong2*)(hdup + 4 * i);
            d[0] = make_ulonglong2(pack2(v.x, v.x), pack2(v.y, v.y));
            d[1] = make_ulonglong2(pack2(v.z, v.z), pack2(v.w, v.w));
        }
        __syncwarp();

        unsigned long long a0 = 0, a1 = 0, a2 = 0, a3 = 0;
        unsigned long long a4 = 0, a5 = 0, a6 = 0, a7 = 0;
        {
            const unsigned long long* wq = Wsu + lane;
            const int k0 = 64 * ks;
#pragma unroll 4
            for (int kk = k0; kk < k0 + 64; kk++) {
                unsigned long long wv = wq[kk * 32];
                const ulonglong2* hq = (const ulonglong2*)(hdup + kk * 8);
                ulonglong2 h01 = hq[0];
                ulonglong2 h23 = hq[1];
                ulonglong2 h45 = hq[2];
                ulonglong2 h67 = hq[3];
                a0 = fma2(h01.x, wv, a0); a1 = fma2(h01.y, wv, a1);
                a2 = fma2(h23.x, wv, a2); a3 = fma2(h23.y, wv, a3);
                a4 = fma2(h45.x, wv, a4); a5 = fma2(h45.y, wv, a5);
                a6 = fma2(h67.x, wv, a6); a7 = fma2(h67.y, wv, a7);
            }
        }

        red[ks * 256 + 0 * 32 + lane] = a0;
        red[ks * 256 + 1 * 32 + lane] = a1;
        red[ks * 256 + 2 * 32 + lane] = a2;
        red[ks * 256 + 3 * 32 + lane] = a3;
        red[ks * 256 + 4 * 32 + lane] = a4;
        red[ks * 256 + 5 * 32 + lane] = a5;
        red[ks * 256 + 6 * 32 + lane] = a6;
        red[ks * 256 + 7 * 32 + lane] = a7;
        __syncthreads();

        float h = 0.f;
        if (tid < 128) {
            const ulonglong2* rp =
                (const ulonglong2*)(red + eb * 32 + ec * 2);
            unsigned long long aif = pack2(z0, z1);
            unsigned long long ago = pack2(z2, z3);
#pragma unroll
            for (int kq = 0; kq < 8; kq++) {
                ulonglong2 v = rp[kq * 128];
                aif = add2(aif, v.x);
                ago = add2(ago, v.y);
            }
            float2 zif = unpack2(aif);
            float2 zgo = unpack2(ago);

            float ig = sigf(zif.x);
            float fg = sigf(zif.y);
            float gg = tanh_fast(zgo.x);
            float og = sigf(zgo.y);
            c = fg * c + ig * gg;
            h = og * tanh_fast(c);

            __stcg(&hdst[hg * BG + eb], h);
            hout[eb * HC + ec] = h;

            asm volatile("bar.sync 1, 128;" ::: "memory");

            if (tid == 0) st_rel(&slots[j], (unsigned)(t + 1));
        }

        if (tid < 32) {
            int bq = tid >> 2;
            int qq = tid & 3;
            float4 hv4 = *(const float4*)&hout[bq * HC + qq * 4];
            *(float4*)&hist[((size_t)(g * BG + bq) * T_ + t) * H_
                            + j * HC + qq * 4] = hv4;
        }
        if (tid < 128) {
            if (t == T_ - 1) {
                c_fin[(size_t)bg * H_ + hg] = c;
                h_fin[(size_t)bg * H_ + hg] = h;
            } else {
                size_t zb = ((size_t)(t + 1) * B_ + bg) * G4H + hg;
                z0 = __ldcs(&g_z0t[zb + 0 * H_]);
                z1 = __ldcs(&g_z0t[zb + 1 * H_]);
                z2 = __ldcs(&g_z0t[zb + 2 * H_]);
                z3 = __ldcs(&g_z0t[zb + 3 * H_]);
            }
        }
    }
}

// ---------------- launch ----------------
extern "C" void kernel_launch(void* const* d_in, const int* in_sizes, int n_in,
                              void* d_out, int out_size) {
    const float* x    = (const float*)d_in[0];
    const float* h0   = (const float*)d_in[1];
    const float* c0   = (const float*)d_in[2];
    const float* Wi   = (const float*)d_in[3];
    const float* Wh   = (const float*)d_in[4];
    const float* bias = (const float*)d_in[5];
    float* out = (float*)d_out;

    const int rec_smem = 512 * 32 * 8 + 512 * 8 * 8 + 8 * 256 * 8 + 128 * 4;
    cudaFuncSetAttribute(lstm_rec, cudaFuncAttributeMaxDynamicSharedMemorySize,
                         rec_smem);

    prep<<<4096, 256>>>(x, Wi, h0);

    dim3 ggrid(G4H / 64, (B_ * T_) / 128);   // (32 N-tiles, 256 M-tiles)
    gemm_xwi<<<ggrid, 256>>>(bias);

    lstm_rec<<<NB, NT, rec_smem>>>(c0, Wh, out);
}